// round 12
// baseline (speedup 1.0000x reference)
#include <cuda_runtime.h>
#include <cuda_bf16.h>

// Problem constants (fixed by reference setup_inputs)
#define HH   1024
#define WW   1024
#define NC   8
#define NCOL (WW * NC)      // 8192 flat columns in [y][x][c] layout
#define NSEG 32
#define SEGH (HH / NSEG)    // 32
#define NPOOL 7

// Scratch: SAT in channel-last layout [y][x][c], fp32. 32 MB (fits L2).
__device__ float g_sat[(size_t)HH * NCOL];
// Decoupled-lookback links per (seg, flat col):
//   {float_bits:32 | flags} flags: bit0 = aggregate ready, bit1 = inclusive.
__device__ unsigned long long g_link[NSEG * NCOL];   // 2 MB

// ---------------------------------------------------------------------------
// Pass 1: inclusive row scan (along x), 4 elements per thread (float4),
// register-sequential prefix + warp scan of totals + 8-warp block combine.
// Transpose to channel-last layout via padded smem for coalesced stores.
// One block (256 threads) per row y. Also resets lookback links (256/row).
// ---------------------------------------------------------------------------
__global__ void __launch_bounds__(256) rowscan_kernel(const float* __restrict__ in) {
    __shared__ float wsum[NC][8];
    __shared__ float sbuf[256 * 33];      // padded transpose buffer (33 KB)

    const int y    = blockIdx.x;
    const int t    = threadIdx.x;
    const int lane = t & 31;
    const int wid  = t >> 5;

    // Reset lookback links: NSEG*NCOL = 262144 entries / 1024 rows = 256 each.
    g_link[(size_t)y * 256 + t] = 0ull;

    // Load 4 consecutive x per channel; sequential in-register prefix.
    float4 v[NC];
    float  tot[NC], excl[NC];
    #pragma unroll
    for (int c = 0; c < NC; ++c) {
        v[c] = ((const float4*)(in + (size_t)c * (HH * WW) + (size_t)y * WW))[t];
        v[c].y += v[c].x;
        v[c].z += v[c].y;
        v[c].w += v[c].z;
        tot[c] = v[c].w;
    }

    // Warp inclusive scan of per-thread totals; derive exclusive offset.
    #pragma unroll
    for (int c = 0; c < NC; ++c) {
        float s = tot[c];
        #pragma unroll
        for (int d = 1; d < 32; d <<= 1) {
            float nb = __shfl_up_sync(0xffffffffu, s, d);
            if (lane >= d) s += nb;
        }
        excl[c] = s - tot[c];
        if (lane == 31) wsum[c][wid] = s;
    }
    __syncthreads();

    // Warp 0 scans the 8 warp totals per channel (width-8 groups).
    if (wid == 0) {
        #pragma unroll
        for (int c = 0; c < NC; ++c) {
            float w = (lane < 8) ? wsum[c][lane] : 0.f;
            #pragma unroll
            for (int d = 1; d < 8; d <<= 1) {
                float nb = __shfl_up_sync(0xffffffffu, w, d);
                if ((lane & 7) >= d) w += nb;
            }
            if (lane < 8) wsum[c][lane] = w;
        }
    }
    __syncthreads();

    // Final values -> padded smem in [x][c] order: idx = 33*t + 8*i + c.
    #pragma unroll
    for (int c = 0; c < NC; ++c) {
        float off = excl[c] + (wid ? wsum[c][wid - 1] : 0.f);
        sbuf[33 * t + c]      = v[c].x + off;
        sbuf[33 * t + 8 + c]  = v[c].y + off;
        sbuf[33 * t + 16 + c] = v[c].z + off;
        sbuf[33 * t + 24 + c] = v[c].w + off;
    }
    __syncthreads();

    // Coalesced float4 stores: output float index o -> smem idx = o + o/32.
    float4* out4 = (float4*)(g_sat + (size_t)y * NCOL);
    #pragma unroll
    for (int j = 0; j < 8; ++j) {
        const int o   = (j * 256 + t) * 4;
        const int idx = o + (o >> 5);
        out4[j * 256 + t] = make_float4(sbuf[idx], sbuf[idx + 1],
                                        sbuf[idx + 2], sbuf[idx + 3]);
    }
}

// ---------------------------------------------------------------------------
// Pass 2: single-pass column cumsum, decoupled lookback with early aggregate
// publish. Block = 1 segment (32 rows) x 256 columns; seg ascends with
// blockIdx (deps point to lower bids -> no deadlock).
// ---------------------------------------------------------------------------
__global__ void __launch_bounds__(256) colscan_kernel() {
    const int tid   = threadIdx.x;
    const int seg   = blockIdx.x >> 5;       // NCOL/256 = 32 chunks per seg
    const int chunk = blockIdx.x & 31;
    const int f     = chunk * 256 + tid;

    float* base = g_sat + (size_t)seg * SEGH * NCOL + f;

    // Local inclusive prefix over the 32 segment rows (reg-resident).
    float pref[SEGH];
    float s = 0.f;
    #pragma unroll
    for (int k = 0; k < SEGH; ++k) {
        s += __ldcg(base + (size_t)k * NCOL);
        pref[k] = s;
    }

    // Publish local aggregate immediately (flag = 1).
    if (seg < NSEG - 1) {
        unsigned long long agg =
            ((unsigned long long)__float_as_uint(s) << 32) | 1ull;
        atomicExch(&g_link[(size_t)seg * NCOL + f], agg);
    }

    // Lookback: walk predecessors, summing aggregates, stop at an inclusive.
    float off = 0.f;
    for (int i = seg - 1; i >= 0; --i) {
        unsigned long long u;
        do {
            u = atomicAdd(&g_link[(size_t)i * NCOL + f], 0ull);
        } while (!(u & 1ull));
        off += __uint_as_float((unsigned)(u >> 32));
        if (u & 2ull) break;       // that value was inclusive -> done
    }

    // Publish inclusive prefix (flag = 3).
    if (seg < NSEG - 1) {
        unsigned long long inc =
            ((unsigned long long)__float_as_uint(off + s) << 32) | 3ull;
        atomicExch(&g_link[(size_t)seg * NCOL + f], inc);
    }

    // Finalize in place.
    #pragma unroll
    for (int k = 0; k < SEGH; ++k)
        __stcg(base + (size_t)k * NCOL, pref[k] + off);
}

// ---------------------------------------------------------------------------
// Pass 3: adaptive 7x7 ROI pooling + final mean. One warp per ROI, task-
// decomposed: 392 tasks = 49 bins x 4 corners x 2 channel-halves, one float4
// gather per task. Even/odd lanes fetch the two halves of the SAME corner
// (same 128B line) -> ~16 distinct lines per LDG instead of ~32, halving L1
// wavefront cost (the measured bottleneck). Reduction: float4 xor-shuffle
// over strides 2..16 (lane parity = channel half), 2 lanes store.
// g_sat holds inclusive SAT; padded sat(y,x) = g_sat[y-1][x-1] (0 at borders).
// ---------------------------------------------------------------------------
__global__ void __launch_bounds__(256) pool_kernel(const int* __restrict__ rois,
                                                   float* __restrict__ out, int n) {
    const int warp = (blockIdx.x * blockDim.x + threadIdx.x) >> 5;
    const int l    = threadIdx.x & 31;
    if (warp >= n) return;

    // rois is int32 [n,4]
    const int4 R = ((const int4*)rois)[warp];
    const int ymin = R.x >> 5;            // // FEAT_STRIDE (=32)
    const int xmin = R.y >> 5;
    const int leny = (R.z >> 5) + 1 - ymin;
    const int lenx = (R.w >> 5) + 1 - xmin;

    const int h = l & 1;                  // channel half (fixed per lane)
    float4 acc = make_float4(0.f, 0.f, 0.f, 0.f);

    #pragma unroll
    for (int k = 0; k < 13; ++k) {
        const int e = 32 * k + l;         // task id
        if (e < 392) {
            const int bin = e >> 3;       // 0..48
            const int c   = (e >> 1) & 3; // corner: 0=(hi,hi) 1=(lo,hi) 2=(hi,lo) 3=(lo,lo)
            const int i   = bin / 7;
            const int j   = bin - i * 7;
            const int ylo = ymin + (i * leny) / NPOOL;
            const int yhi = ymin + ((i + 1) * leny + NPOOL - 1) / NPOOL;
            const int xlo = xmin + (j * lenx) / NPOOL;
            const int xhi = xmin + ((j + 1) * lenx + NPOOL - 1) / NPOOL;

            const int yy = (c & 1) ? ylo : yhi;
            const int xx = (c & 2) ? xlo : xhi;

            float w = 1.f / (float)((yhi - ylo) * (xhi - xlo));
            if ((c ^ (c >> 1)) & 1) w = -w;   // corners 1,2 negative

            float4 v = make_float4(0.f, 0.f, 0.f, 0.f);
            if (yy > 0 && xx > 0)
                v = *(const float4*)(g_sat + ((size_t)(yy - 1) * WW + (xx - 1)) * NC + h * 4);

            acc.x += w * v.x; acc.y += w * v.y;
            acc.z += w * v.z; acc.w += w * v.w;
        }
    }

    // Reduce across lanes of same parity (strides 2..16 preserve parity).
    #pragma unroll
    for (int d = 2; d <= 16; d <<= 1) {
        acc.x += __shfl_xor_sync(0xffffffffu, acc.x, d);
        acc.y += __shfl_xor_sync(0xffffffffu, acc.y, d);
        acc.z += __shfl_xor_sync(0xffffffffu, acc.z, d);
        acc.w += __shfl_xor_sync(0xffffffffu, acc.w, d);
    }

    if (l < 2) {
        const float s = 1.f / 49.f;
        ((float4*)(out + (size_t)warp * 8))[l] =
            make_float4(acc.x * s, acc.y * s, acc.z * s, acc.w * s);
    }
}

// ---------------------------------------------------------------------------
extern "C" void kernel_launch(void* const* d_in, const int* in_sizes, int n_in,
                              void* d_out, int out_size) {
    const float* conv = (const float*)d_in[0];   // [8,1024,1024] fp32
    const int*   rois = (const int*)d_in[1];     // [n,4] int32
    float*       out  = (float*)d_out;           // [n,8] fp32
    const int n = in_sizes[1] / 4;

    rowscan_kernel<<<HH, 256>>>(conv);
    colscan_kernel<<<NSEG * (NCOL / 256), 256>>>();
    pool_kernel   <<<(n + 7) / 8, 256>>>(rois, out, n);
}